// round 10
// baseline (speedup 1.0000x reference)
#include <cuda_runtime.h>
#include <cuda_fp16.h>

typedef unsigned int u32;

#define IMH 512
#define IMW 512
#define TW 128              // tile width (2 px per thread, 64 pairs/rowgroup)
#define TY 8
#define NCOLS 136           // TW + 8 halo
#define PITCH 137           // UV pitch (half2)
#define YPITCH 138          // luma pitch (halves), even for u32 loads
#define NROWS 16            // TY + 8
#define NGRP 66             // odd-start 4-column groups per rowgroup
#define NCOLSORT (8 * NCOLS)   // 1088 column sorts per block
#define NGRPTOT  (8 * NGRP)    // 528 group builds per block

// smem layout (bytes): [sCol 39168][sY 4416 | sUV 8768] ; sGrp (76032,
// row-major [group][36]) overlaps the Y/UV region (dead before sGrp writes).
#define OFF_Y    39168
#define OFF_UV   (OFF_Y + YPITCH * NROWS * 2)    // 43584
#define OFF_GRP  39168
#define SMEM_TOTAL (39168 + 36 * NGRPTOT * 4)    // 115200

__device__ __forceinline__ void ce2(__half2& a, __half2& b) {
    __half2 lo = __hmin2(a, b);
    __half2 hi = __hmax2(a, b);
    a = lo;
    b = hi;
}

__device__ __forceinline__ __half2 u2h(u32 u) {
    __half2 h;
    *reinterpret_cast<u32*>(&h) = u;
    return h;
}
__device__ __forceinline__ u32 h2u(__half2 h) {
    return *reinterpret_cast<u32*>(&h);
}

// Ascending bitonic merge stages over t[0..L) with virtual +inf padding to the
// next power of two. Input must be bitonic: [descending | ascending | +inf...].
template <int L, int S>
__device__ __forceinline__ void bstages(__half2 (&t)[L]) {
    if constexpr (S >= 1) {
#pragma unroll
        for (int i = 0; i + S < L; i++)
            if ((i & S) == 0) ce2(t[i], t[i + S]);
        bstages<L, S / 2>(t);
    }
}

// sort9 in 29 CEs: 3x sort3, merge(3,3)->6, merge(6,3)->9.
__device__ __forceinline__ void sort9(__half2 (&v)[9]) {
#pragma unroll
    for (int b = 0; b < 9; b += 3) {
        ce2(v[b], v[b + 1]); ce2(v[b + 1], v[b + 2]); ce2(v[b], v[b + 1]);
    }
    __half2 m[6] = {v[2], v[1], v[0], v[3], v[4], v[5]};   // [desc3 | asc3]
    bstages<6, 4>(m);
    __half2 t[9] = {m[5], m[4], m[3], m[2], m[1], m[0],    // [desc6 | asc3]
                    v[6], v[7], v[8]};
    bstages<9, 8>(t);
#pragma unroll
    for (int k = 0; k < 9; k++) v[k] = t[k];
}

__device__ __forceinline__ int reflect_idx(int i, int n) {
    if (i < 0) i = -1 - i;          // numpy 'symmetric'
    if (i >= n) i = 2 * n - 1 - i;
    return i;
}

__global__ void __launch_bounds__(512, 2)
denoise_median_kernel(const float* __restrict__ img, float* __restrict__ out) {
    extern __shared__ char smem_raw[];
    __half2* sColT = (__half2*)smem_raw;                 // [rank][rg*136+col]
    __half*  sYh   = (__half*)(smem_raw + OFF_Y);        // luma fp16, +1 shift
    __half2* sUV   = (__half2*)(smem_raw + OFF_UV);      // (U,V) packed
    __half2* sGrp  = (__half2*)(smem_raw + OFF_GRP);     // [group][36]

    const int bx = blockIdx.x * TW;
    const int by = blockIdx.y * TY;
    const int bat = blockIdx.z;
    const int tid = threadIdx.x;

    const float* Rp = img + (size_t)bat * 3 * IMH * IMW;
    const float* Gp = Rp + IMH * IMW;
    const float* Bp = Gp + IMH * IMW;

    // ---- Phase 1: load halo tile (136 x 16), RGB->YUV on the fly ----
    for (int idx = tid; idx < NROWS * NCOLS; idx += 512) {
        int r = idx / NCOLS;
        int c = idx % NCOLS;
        int gy = reflect_idx(by - 4 + r, IMH);
        int gx = reflect_idx(bx - 4 + c, IMW);
        float R = Rp[gy * IMW + gx];
        float G = Gp[gy * IMW + gx];
        float B = Bp[gy * IMW + gx];
        float Y = 0.299f * R + 0.587f * G + 0.114f * B;
        float U = -0.14713f * R - 0.28886f * G + 0.436f * B;
        float V = 0.615f * R - 0.51499f * G - 0.10001f * B;
        sYh[r * YPITCH + c + 1] = __float2half(Y);       // +1 column shift
        sUV[r * PITCH + c] = __floats2half2_rn(U, V);
    }
    __syncthreads();

    const int tp = tid & 63;          // pixel-pair index within rowgroup
    const int ty = tid >> 6;          // rowgroup
    const int c0 = 2 * tp;            // left pixel's local halo column

    // ---- Phase 2a: luma (both pixels, one half2 3x3 network) -> registers ----
    // Per window row: halves at shifted indices c0+4..c0+7 via two aligned u32.
    __half2 pl[9];
#pragma unroll
    for (int rr = 0; rr < 3; rr++) {
        const u32* wp =
            (const u32*)(sYh + (ty + 3 + rr) * YPITCH + c0 + 4);
        u32 w0 = wp[0];                            // (x0,x1)
        u32 w1 = wp[1];                            // (x2,x3)
        pl[rr * 3 + 0] = u2h(w0);                  // (x0,x1)
        pl[rr * 3 + 1] = u2h(__byte_perm(w0, w1, 0x5432));  // (x1,x2)
        pl[rr * 3 + 2] = u2h(w1);                  // (x2,x3)
    }
    ce2(pl[1], pl[2]); ce2(pl[4], pl[5]); ce2(pl[7], pl[8]);
    ce2(pl[0], pl[1]); ce2(pl[3], pl[4]); ce2(pl[6], pl[7]);
    ce2(pl[1], pl[2]); ce2(pl[4], pl[5]); ce2(pl[7], pl[8]);
    ce2(pl[0], pl[3]); ce2(pl[5], pl[8]); ce2(pl[4], pl[7]);
    ce2(pl[3], pl[6]); ce2(pl[1], pl[4]); ce2(pl[2], pl[5]);
    ce2(pl[4], pl[7]); ce2(pl[4], pl[2]); ce2(pl[6], pl[4]);
    ce2(pl[4], pl[2]);
    __half2 ylum2 = __hmin2(__hmax2(pl[4], __floats2half2_rn(0.f, 0.f)),
                            __floats2half2_rn(1.f, 1.f));

    // ---- Phase 2b: sorted 9-columns into transposed sCol ----
    for (int idx = tid; idx < NCOLSORT; idx += 512) {
        int rg = idx / NCOLS;
        int c = idx % NCOLS;
        __half2 v[9];
#pragma unroll
        for (int k = 0; k < 9; k++) v[k] = sUV[(rg + k) * PITCH + c];
        sort9(v);
#pragma unroll
        for (int k = 0; k < 9; k++) sColT[k * NCOLSORT + idx] = v[k];
    }
    __syncthreads();   // sY/sUV dead from here; sGrp overwrites them

    // ---- Phase 2.5: sorted-36 groups of 4 columns, built ONCE each ----
    for (int idx = tid; idx < NGRPTOT; idx += 512) {
        int rg = idx / NGRP;
        int g = idx % NGRP;
        int s = 2 * g + 1;
        const int cbase = rg * NCOLS;
        __half2 r0[18], r1[18];
#pragma unroll
        for (int k = 0; k < 9; k++) {
            r0[k]     = sColT[(8 - k) * NCOLSORT + cbase + s + 0];  // desc
            r0[9 + k] = sColT[k * NCOLSORT + cbase + s + 1];        // asc
            r1[k]     = sColT[(8 - k) * NCOLSORT + cbase + s + 2];
            r1[9 + k] = sColT[k * NCOLSORT + cbase + s + 3];
        }
        bstages<18, 16>(r0);
        bstages<18, 16>(r1);
        __half2 A[36];
#pragma unroll
        for (int k = 0; k < 18; k++) {
            A[k]      = r0[17 - k];
            A[18 + k] = r1[k];
        }
        bstages<36, 32>(A);
        uint4* dst = reinterpret_cast<uint4*>(sGrp + idx * 36);
#pragma unroll
        for (int q = 0; q < 9; q++) {
            uint4 u;
            u.x = h2u(A[4 * q + 0]);
            u.y = h2u(A[4 * q + 1]);
            u.z = h2u(A[4 * q + 2]);
            u.w = h2u(A[4 * q + 3]);
            dst[q] = u;
        }
    }
    __syncthreads();

    // ---- Phase 3: pruned 72-merge of the two shared groups ----
    const int gAi = ty * NGRP + tp;       // cols c0+1..c0+4
    const int gBi = gAi + 2;              // cols c0+5..c0+8

    __half2 T[72];
    {
        const uint4* pa = reinterpret_cast<const uint4*>(sGrp + gAi * 36);
#pragma unroll
        for (int q = 0; q < 9; q++) {
            uint4 u = pa[q];
            T[35 - (4 * q + 0)] = u2h(u.x);    // descending half
            T[35 - (4 * q + 1)] = u2h(u.y);
            T[35 - (4 * q + 2)] = u2h(u.z);
            T[35 - (4 * q + 3)] = u2h(u.w);
        }
        const uint4* pb = reinterpret_cast<const uint4*>(sGrp + gBi * 36);
#pragma unroll
        for (int q = 0; q < 9; q++) {
            uint4 u = pb[q];
            T[36 + 4 * q + 0] = u2h(u.x);      // ascending half
            T[36 + 4 * q + 1] = u2h(u.y);
            T[36 + 4 * q + 2] = u2h(u.z);
            T[36 + 4 * q + 3] = u2h(u.w);
        }
    }
    bstages<72, 64>(T);   // only ranks 31..40 consumed -> DCE prunes cone

    // ---- Per-pixel: add private column via rank-40 selection identity ----
    // merged[40] = max_{i+j=40} min(T[i], col[j]), OOR -> +inf.
    const int cbase = ty * NCOLS;
    __half2 mL = T[31], mR = T[31];
#pragma unroll
    for (int k = 1; k <= 9; k++) {
        mL = __hmax2(mL, __hmin2(T[31 + k], sColT[(9 - k) * NCOLSORT + cbase + c0]));
        mR = __hmax2(mR, __hmin2(T[31 + k], sColT[(9 - k) * NCOLSORT + cbase + c0 + 9]));
    }

    // ---- YUV -> RGB, vectorized pair store ----
    float ylumL = __low2float(ylum2);
    float ylumR = __high2float(ylum2);
    float uL = __low2float(mL), vL = __high2float(mL);
    float uR = __low2float(mR), vR = __high2float(mR);

    float2 Rv = make_float2(ylumL + 1.13983f * vL, ylumR + 1.13983f * vR);
    float2 Gv = make_float2(ylumL - 0.39465f * uL - 0.5806f * vL,
                            ylumR - 0.39465f * uR - 0.5806f * vR);
    float2 Bv = make_float2(ylumL + 2.03211f * uL, ylumR + 2.03211f * uR);

    const int gy = by + ty;
    const int gx = bx + c0;
    size_t o = (size_t)bat * 3 * IMH * IMW + (size_t)gy * IMW + gx;
    *(float2*)(out + o) = Rv;
    *(float2*)(out + o + IMH * IMW) = Gv;
    *(float2*)(out + o + 2 * IMH * IMW) = Bv;
}

extern "C" void kernel_launch(void* const* d_in, const int* in_sizes, int n_in,
                              void* d_out, int out_size) {
    const float* img = (const float*)d_in[0];
    float* out = (float*)d_out;
    int batch = in_sizes[0] / (3 * IMH * IMW);
    cudaFuncSetAttribute(denoise_median_kernel,
                         cudaFuncAttributeMaxDynamicSharedMemorySize, SMEM_TOTAL);
    dim3 grid(IMW / TW, IMH / TY, batch);
    denoise_median_kernel<<<grid, 512, SMEM_TOTAL>>>(img, out);
}

// round 11
// speedup vs baseline: 1.1301x; 1.1301x over previous
#include <cuda_runtime.h>
#include <cuda_fp16.h>

typedef unsigned int u32;

#define IMH 512
#define IMW 512
#define TW 128              // tile width (2 px per thread, 64 pairs/rowgroup)
#define TY 8
#define NCOLS 136           // TW + 8 halo
#define HALFC 68            // columns per parity
#define YPITCH 138          // luma pitch (halves), even for u32 loads
#define NROWS 16            // TY + 8
#define NGRP 66             // odd-start 4-column groups per rowgroup
#define NGRPTOT  (8 * NGRP)    // 528 group builds per block
#define NTHREADS 544
#define CSTRIDE 544         // per-rank stride in parity column arrays (8*68)

// smem layout (bytes):
//  [sColE 19584][sColO 19584] = 39168
//  then EITHER [sY 4416][sUVE 4352][sUVO 4352] (phases 1-2b)
//  OR sGrp 76032 (row-major [group][36]) overlapping it (phases 2.5-3).
#define OFF_COLO 19584
#define OFF_Y    39168
#define OFF_UVE  (OFF_Y + YPITCH * NROWS * 2)    // 43584
#define OFF_UVO  (OFF_UVE + NROWS * HALFC * 4)   // 47936
#define OFF_GRP  39168
#define SMEM_TOTAL (OFF_GRP + 36 * NGRPTOT * 4)  // 115200

__device__ __forceinline__ void ce2(__half2& a, __half2& b) {
    __half2 lo = __hmin2(a, b);
    __half2 hi = __hmax2(a, b);
    a = lo;
    b = hi;
}

__device__ __forceinline__ __half2 u2h(u32 u) {
    __half2 h;
    *reinterpret_cast<u32*>(&h) = u;
    return h;
}
__device__ __forceinline__ u32 h2u(__half2 h) {
    return *reinterpret_cast<u32*>(&h);
}

// Ascending bitonic merge stages over t[0..L) with virtual +inf padding to the
// next power of two. Input must be bitonic: [descending | ascending | +inf...].
template <int L, int S>
__device__ __forceinline__ void bstages(__half2 (&t)[L]) {
    if constexpr (S >= 1) {
#pragma unroll
        for (int i = 0; i + S < L; i++)
            if ((i & S) == 0) ce2(t[i], t[i + S]);
        bstages<L, S / 2>(t);
    }
}

// sort9 in 29 CEs: 3x sort3, merge(3,3)->6, merge(6,3)->9.
__device__ __forceinline__ void sort9(__half2 (&v)[9]) {
#pragma unroll
    for (int b = 0; b < 9; b += 3) {
        ce2(v[b], v[b + 1]); ce2(v[b + 1], v[b + 2]); ce2(v[b], v[b + 1]);
    }
    __half2 m[6] = {v[2], v[1], v[0], v[3], v[4], v[5]};   // [desc3 | asc3]
    bstages<6, 4>(m);
    __half2 t[9] = {m[5], m[4], m[3], m[2], m[1], m[0],    // [desc6 | asc3]
                    v[6], v[7], v[8]};
    bstages<9, 8>(t);
#pragma unroll
    for (int k = 0; k < 9; k++) v[k] = t[k];
}

__device__ __forceinline__ int reflect_idx(int i, int n) {
    if (i < 0) i = -1 - i;          // numpy 'symmetric'
    if (i >= n) i = 2 * n - 1 - i;
    return i;
}

__global__ void __launch_bounds__(NTHREADS, 2)
denoise_median_kernel(const float* __restrict__ img, float* __restrict__ out) {
    extern __shared__ char smem_raw[];
    __half2* sColE = (__half2*)smem_raw;                 // [rank][rg*68+m]
    __half2* sColO = (__half2*)(smem_raw + OFF_COLO);
    __half*  sYh   = (__half*)(smem_raw + OFF_Y);        // luma fp16, +1 shift
    __half2* sUVE  = (__half2*)(smem_raw + OFF_UVE);     // even cols (U,V)
    __half2* sUVO  = (__half2*)(smem_raw + OFF_UVO);     // odd cols
    __half2* sGrp  = (__half2*)(smem_raw + OFF_GRP);     // [group][36]

    const int bx = blockIdx.x * TW;
    const int by = blockIdx.y * TY;
    const int bat = blockIdx.z;
    const int tid = threadIdx.x;

    const float* Rp = img + (size_t)bat * 3 * IMH * IMW;
    const float* Gp = Rp + IMH * IMW;
    const float* Bp = Gp + IMH * IMW;

    const int mm = tid % HALFC;       // parity-column index
    const int rr8 = tid / HALFC;      // 0..7

    // ---- Phase 1: load halo tile (136 x 16), RGB->YUV; exactly 4 iters ----
#pragma unroll
    for (int it = 0; it < 4; it++) {
        int p = it & 1;
        int r = (it >> 1) * 8 + rr8;
        int c = 2 * mm + p;
        int gy = reflect_idx(by - 4 + r, IMH);
        int gx = reflect_idx(bx - 4 + c, IMW);
        float R = Rp[gy * IMW + gx];
        float G = Gp[gy * IMW + gx];
        float B = Bp[gy * IMW + gx];
        float Y = 0.299f * R + 0.587f * G + 0.114f * B;
        float U = -0.14713f * R - 0.28886f * G + 0.436f * B;
        float V = 0.615f * R - 0.51499f * G - 0.10001f * B;
        sYh[r * YPITCH + c + 1] = __float2half(Y);       // +1 column shift
        __half2* uvp = p ? sUVO : sUVE;
        uvp[r * HALFC + mm] = __floats2half2_rn(U, V);
    }
    __syncthreads();

    const int tp = tid & 63;          // pixel-pair index within rowgroup
    const int ty = tid >> 6;          // rowgroup (valid for tid < 512)
    const int c0 = 2 * tp;            // left pixel's local halo column

    // ---- Phase 2a: luma (both pixels, one half2 3x3 network) -> registers ----
    __half2 ylum2;
    if (tid < 512) {
        __half2 pl[9];
#pragma unroll
        for (int rw = 0; rw < 3; rw++) {
            const u32* wp =
                (const u32*)(sYh + (ty + 3 + rw) * YPITCH + c0 + 4);
            u32 w0 = wp[0];
            u32 w1 = wp[1];
            pl[rw * 3 + 0] = u2h(w0);
            pl[rw * 3 + 1] = u2h(__byte_perm(w0, w1, 0x5432));
            pl[rw * 3 + 2] = u2h(w1);
        }
        ce2(pl[1], pl[2]); ce2(pl[4], pl[5]); ce2(pl[7], pl[8]);
        ce2(pl[0], pl[1]); ce2(pl[3], pl[4]); ce2(pl[6], pl[7]);
        ce2(pl[1], pl[2]); ce2(pl[4], pl[5]); ce2(pl[7], pl[8]);
        ce2(pl[0], pl[3]); ce2(pl[5], pl[8]); ce2(pl[4], pl[7]);
        ce2(pl[3], pl[6]); ce2(pl[1], pl[4]); ce2(pl[2], pl[5]);
        ce2(pl[4], pl[7]); ce2(pl[4], pl[2]); ce2(pl[6], pl[4]);
        ce2(pl[4], pl[2]);
        ylum2 = __hmin2(__hmax2(pl[4], __floats2half2_rn(0.f, 0.f)),
                        __floats2half2_rn(1.f, 1.f));
    }

    // ---- Phase 2b: sorted 9-columns; exactly 2 per thread, conflict-free ----
#pragma unroll
    for (int it = 0; it < 2; it++) {
        const __half2* src = it ? sUVO : sUVE;
        __half2* dst = it ? sColO : sColE;
        __half2 v[9];
#pragma unroll
        for (int k = 0; k < 9; k++) v[k] = src[(rr8 + k) * HALFC + mm];
        sort9(v);
#pragma unroll
        for (int k = 0; k < 9; k++) dst[k * CSTRIDE + tid] = v[k];
    }
    __syncthreads();   // Y/UV dead from here; sGrp overwrites them

    // ---- Phase 2.5: sorted-36 groups of 4 columns; <=1 per thread ----
    if (tid < NGRPTOT) {
        const int rg = tid / NGRP;
        const int g = tid % NGRP;
        const int cb = rg * HALFC;
        // cols s..s+3 = odd(g), even(g+1), odd(g+1), even(g+2)
        __half2 r0[18], r1[18];
#pragma unroll
        for (int k = 0; k < 9; k++) {
            r0[k]     = sColO[(8 - k) * CSTRIDE + cb + g];        // desc
            r0[9 + k] = sColE[k * CSTRIDE + cb + g + 1];          // asc
            r1[k]     = sColO[(8 - k) * CSTRIDE + cb + g + 1];
            r1[9 + k] = sColE[k * CSTRIDE + cb + g + 2];
        }
        bstages<18, 16>(r0);
        bstages<18, 16>(r1);
        __half2 A[36];
#pragma unroll
        for (int k = 0; k < 18; k++) {
            A[k]      = r0[17 - k];
            A[18 + k] = r1[k];
        }
        bstages<36, 32>(A);
        uint4* dst = reinterpret_cast<uint4*>(sGrp + tid * 36);
#pragma unroll
        for (int q = 0; q < 9; q++) {
            uint4 u;
            u.x = h2u(A[4 * q + 0]);
            u.y = h2u(A[4 * q + 1]);
            u.z = h2u(A[4 * q + 2]);
            u.w = h2u(A[4 * q + 3]);
            dst[q] = u;
        }
    }
    __syncthreads();

    if (tid >= 512) return;

    // ---- Phase 3: pruned 72-merge of the two shared groups ----
    const int gAi = ty * NGRP + tp;       // cols c0+1..c0+4
    const int gBi = gAi + 2;              // cols c0+5..c0+8

    __half2 T[72];
    {
        const uint4* pa = reinterpret_cast<const uint4*>(sGrp + gAi * 36);
#pragma unroll
        for (int q = 0; q < 9; q++) {
            uint4 u = pa[q];
            T[35 - (4 * q + 0)] = u2h(u.x);    // descending half
            T[35 - (4 * q + 1)] = u2h(u.y);
            T[35 - (4 * q + 2)] = u2h(u.z);
            T[35 - (4 * q + 3)] = u2h(u.w);
        }
        const uint4* pb = reinterpret_cast<const uint4*>(sGrp + gBi * 36);
#pragma unroll
        for (int q = 0; q < 9; q++) {
            uint4 u = pb[q];
            T[36 + 4 * q + 0] = u2h(u.x);      // ascending half
            T[36 + 4 * q + 1] = u2h(u.y);
            T[36 + 4 * q + 2] = u2h(u.z);
            T[36 + 4 * q + 3] = u2h(u.w);
        }
    }
    bstages<72, 64>(T);   // only ranks 31..40 consumed -> DCE prunes cone

    // ---- Per-pixel: add private column via rank-40 selection identity ----
    // merged[40] = max_{i+j=40} min(T[i], col[j]), OOR -> +inf.
    const int cbE = ty * HALFC + tp;       // colL = even col, m=tp
    const int cbO = ty * HALFC + tp + 4;   // colR = odd col 2tp+9, m=tp+4
    __half2 mL = T[31], mR = T[31];
#pragma unroll
    for (int k = 1; k <= 9; k++) {
        mL = __hmax2(mL, __hmin2(T[31 + k], sColE[(9 - k) * CSTRIDE + cbE]));
        mR = __hmax2(mR, __hmin2(T[31 + k], sColO[(9 - k) * CSTRIDE + cbO]));
    }

    // ---- YUV -> RGB, vectorized pair store ----
    float ylumL = __low2float(ylum2);
    float ylumR = __high2float(ylum2);
    float uL = __low2float(mL), vL = __high2float(mL);
    float uR = __low2float(mR), vR = __high2float(mR);

    float2 Rv = make_float2(ylumL + 1.13983f * vL, ylumR + 1.13983f * vR);
    float2 Gv = make_float2(ylumL - 0.39465f * uL - 0.5806f * vL,
                            ylumR - 0.39465f * uR - 0.5806f * vR);
    float2 Bv = make_float2(ylumL + 2.03211f * uL, ylumR + 2.03211f * uR);

    const int gy = by + ty;
    const int gx = bx + c0;
    size_t o = (size_t)bat * 3 * IMH * IMW + (size_t)gy * IMW + gx;
    *(float2*)(out + o) = Rv;
    *(float2*)(out + o + IMH * IMW) = Gv;
    *(float2*)(out + o + 2 * IMH * IMW) = Bv;
}

extern "C" void kernel_launch(void* const* d_in, const int* in_sizes, int n_in,
                              void* d_out, int out_size) {
    const float* img = (const float*)d_in[0];
    float* out = (float*)d_out;
    int batch = in_sizes[0] / (3 * IMH * IMW);
    cudaFuncSetAttribute(denoise_median_kernel,
                         cudaFuncAttributeMaxDynamicSharedMemorySize, SMEM_TOTAL);
    dim3 grid(IMW / TW, IMH / TY, batch);
    denoise_median_kernel<<<grid, NTHREADS, SMEM_TOTAL>>>(img, out);
}